// round 15
// baseline (speedup 1.0000x reference)
#include <cuda_runtime.h>
#include <cuda_bf16.h>
#include <cuda_fp16.h>
#include <cstdint>

// Problem constants
constexpr int Bn  = 2;
constexpr int Ln  = 2048;
constexpr int Dn  = 1024;
constexpr int Hn  = 16;
constexpr int HDn = 64;
constexpr int NROW = Bn * Ln;   // 4096
constexpr size_t PLANE = (size_t)Bn * Hn * Ln * HDn;  // 4M elems

// Scaling
constexpr float SC_X = 16.f;
constexpr float SC_W = 32.f;
constexpr float SC_Y = 256.f;
constexpr float INV_QKV = 1.f / (16.f * 32.f);    // 1/512
constexpr float INV_OUT = 1.f / (256.f * 32.f);   // 1/8192

// Scratch (device globals: allocation-free)
__device__ uint16_t g_x16[(size_t)NROW * Dn];     // fp16 of 16*x, [m][k]
__device__ uint16_t g_w16[(size_t)4 * Dn * Dn];   // fp16(32W): Wq,Wk,Wv,Wo [k][n]
__device__ uint16_t g_q16[PLANE];                 // fp16 of 0.5*q, [B,H,L,HD]
__device__ uint16_t g_k16[PLANE];                 // fp16 of 0.25*k
__device__ uint16_t g_v16[PLANE];                 // fp16 of v
__device__ uint16_t g_y16[(size_t)NROW * Dn];     // fp16 of 256*y

// ---------------------------------------------------------------------------
// Helpers
// ---------------------------------------------------------------------------
__device__ __forceinline__ uint32_t s2u(const void* p) {
    uint32_t a;
    asm("{ .reg .u64 t; cvta.to.shared.u64 t, %1; cvt.u32.u64 %0, t; }"
        : "=r"(a) : "l"(p));
    return a;
}
__device__ __forceinline__ void cp16(uint32_t dst, const void* src) {
    asm volatile("cp.async.cg.shared.global [%0], [%1], 16;"
                 :: "r"(dst), "l"(src) : "memory");
}
#define CP_COMMIT() asm volatile("cp.async.commit_group;" ::: "memory")
#define CP_WAIT0()  asm volatile("cp.async.wait_group 0;" ::: "memory")

__device__ __forceinline__ void ldm_x4(uint32_t* r, uint32_t a) {
    asm volatile("ldmatrix.sync.aligned.m8n8.x4.shared.b16 {%0,%1,%2,%3}, [%4];"
                 : "=r"(r[0]), "=r"(r[1]), "=r"(r[2]), "=r"(r[3]) : "r"(a));
}
__device__ __forceinline__ void ldm_x4t(uint32_t* r, uint32_t a) {
    asm volatile("ldmatrix.sync.aligned.m8n8.x4.trans.shared.b16 {%0,%1,%2,%3}, [%4];"
                 : "=r"(r[0]), "=r"(r[1]), "=r"(r[2]), "=r"(r[3]) : "r"(a));
}
__device__ __forceinline__ void mma_f16(float* c, const uint32_t* a,
                                        const uint32_t* b) {
    asm volatile(
        "mma.sync.aligned.m16n8k16.row.col.f32.f16.f16.f32 "
        "{%0,%1,%2,%3}, {%4,%5,%6,%7}, {%8,%9}, {%0,%1,%2,%3};"
        : "+f"(c[0]), "+f"(c[1]), "+f"(c[2]), "+f"(c[3])
        : "r"(a[0]), "r"(a[1]), "r"(a[2]), "r"(a[3]), "r"(b[0]), "r"(b[1]));
}
// fp16 helpers
__device__ __forceinline__ uint16_t hfu(float f) {
    __half h = __float2half_rn(f);
    return *(uint16_t*)&h;
}
__device__ __forceinline__ uint2 pack4h(float4 v) {
    uint16_t h0 = hfu(v.x), h1 = hfu(v.y), h2 = hfu(v.z), h3 = hfu(v.w);
    return make_uint2((uint32_t)h0 | ((uint32_t)h1 << 16),
                      (uint32_t)h2 | ((uint32_t)h3 << 16));
}
__device__ __forceinline__ uint32_t pack2h(float f0, float f1) {
    return (uint32_t)hfu(f0) | ((uint32_t)hfu(f1) << 16);
}

// ---------------------------------------------------------------------------
// Prep: x -> fp16(16x) single [m][k]; all 4 weights -> fp16(32W) [k][n].
// ---------------------------------------------------------------------------
__global__ void __launch_bounds__(256) prep_kernel(
    const float* __restrict__ x,
    const float* __restrict__ Wq, const float* __restrict__ Wk,
    const float* __restrict__ Wv, const float* __restrict__ Wo)
{
    int i = blockIdx.x * 256 + threadIdx.x;   // float4 index
    if (i < (1 << 20)) {
        float4 v = ((const float4*)x)[i];
        v.x *= SC_X; v.y *= SC_X; v.z *= SC_X; v.w *= SC_X;
        ((uint2*)g_x16)[i] = pack4h(v);
    } else {
        int j = i - (1 << 20);
        int slot = j >> 18;
        int off  = j & ((1 << 18) - 1);
        const float* w = (slot == 0) ? Wq : (slot == 1) ? Wk
                        : (slot == 2) ? Wv : Wo;
        float4 v = ((const float4*)w)[off];
        v.x *= SC_W; v.y *= SC_W; v.z *= SC_W; v.w *= SC_W;
        ((uint2*)g_w16)[((size_t)slot << 18) + off] = pack4h(v);
    }
}

// ---------------------------------------------------------------------------
// fp16 1-pass GEMM v2 (unchanged from round 14): 128x128 CTA, 8 warps (2m x 4n),
// warp tile 64x32, BK=64, 2-stage cp.async.
// Stage (bytes): A [0,18432) 128x144B; B [18432,35840) 64x272B. 2 CTAs/SM.
// ---------------------------------------------------------------------------
constexpr int G_STAGE = 35840;
constexpr int GEMM_SMEM_BYTES = 2 * G_STAGE;   // 71680

__global__ void __launch_bounds__(256, 2) gemm_mma_kernel(
    float* __restrict__ outp, int mode)
{
    extern __shared__ uint16_t smg[];
    const uint32_t sb = s2u(smg);

    const int tid  = threadIdx.x;
    const int lane = tid & 31;
    const int w    = tid >> 5;
    const int wm   = w >> 2;
    const int wn   = w & 3;
    const int col0 = blockIdx.x * 128;
    const int row0 = blockIdx.y * 128;
    const int z    = blockIdx.z;

    const uint16_t* Ap = (mode == 0) ? g_x16 : g_y16;
    const int slot = (mode == 0) ? z : 3;
    const uint16_t* Bp = g_w16 + ((size_t)slot << 20);

    float C[4][4][4];
    #pragma unroll
    for (int mi = 0; mi < 4; mi++)
        #pragma unroll
        for (int ni = 0; ni < 4; ni++)
            #pragma unroll
            for (int q = 0; q < 4; q++) C[mi][ni][q] = 0.f;

    auto issue = [&](int c_, int s_) {
        uint32_t dstb = sb + (uint32_t)s_ * G_STAGE;
        int k0 = c_ * 64;
        #pragma unroll
        for (int i = 0; i < 4; i++) {
            int local = i * 256 + tid;
            int r = local >> 3, cc = local & 7;
            uint32_t dst = dstb + (uint32_t)(r * 144 + cc * 16);
            cp16(dst, Ap + (size_t)(row0 + r) * Dn + k0 + cc * 8);
        }
        #pragma unroll
        for (int i = 0; i < 4; i++) {
            int local = i * 256 + tid;
            int kk = local >> 4, cc = local & 15;
            uint32_t dst = dstb + 18432u + (uint32_t)(kk * 272 + cc * 16);
            cp16(dst, Bp + (size_t)(k0 + kk) * Dn + col0 + cc * 8);
        }
    };

    issue(0, 0);
    CP_COMMIT();

    for (int c = 0; c < 16; c++) {
        CP_WAIT0();
        __syncthreads();
        if (c + 1 < 16) {
            issue(c + 1, (c + 1) & 1);
            CP_COMMIT();
        }
        const uint32_t stgb = sb + (uint32_t)(c & 1) * G_STAGE;

        #pragma unroll
        for (int ks = 0; ks < 4; ks++) {
            uint32_t af[4][4], bf[4][2];
            #pragma unroll
            for (int mi = 0; mi < 4; mi++) {
                uint32_t off = (uint32_t)((wm * 64 + mi * 16 + (lane & 15)) * 144
                                          + ks * 32 + ((lane >> 4) * 16));
                ldm_x4(af[mi], stgb + off);
            }
            #pragma unroll
            for (int g = 0; g < 2; g++) {
                uint32_t off = 18432u
                    + (uint32_t)((ks * 16 + (lane & 15)) * 272
                                 + (wn * 32 + g * 16 + ((lane >> 4) * 8)) * 2);
                uint32_t t[4];
                ldm_x4t(t, stgb + off);
                bf[g*2][0]   = t[0]; bf[g*2][1]   = t[1];
                bf[g*2+1][0] = t[2]; bf[g*2+1][1] = t[3];
            }
            #pragma unroll
            for (int mi = 0; mi < 4; mi++)
                #pragma unroll
                for (int ni = 0; ni < 4; ni++)
                    mma_f16(C[mi][ni], af[mi], bf[ni]);
        }
        __syncthreads();
    }

    if (mode == 0) {
        const float s = INV_QKV * ((z == 0) ? 0.5f : (z == 1) ? 0.25f : 1.f);
        uint16_t* dst = (z == 0) ? g_q16 : (z == 1) ? g_k16 : g_v16;
        #pragma unroll
        for (int mi = 0; mi < 4; mi++)
            #pragma unroll
            for (int ni = 0; ni < 4; ni++) {
                int row = row0 + wm * 64 + mi * 16 + (lane >> 2);
                int col = col0 + wn * 32 + ni * 8 + (lane & 3) * 2;
                int hh = col >> 6, hd = col & 63;
                #pragma unroll
                for (int half = 0; half < 2; half++) {
                    int r = row + half * 8;
                    int b = r >> 11, l = r & 2047;
                    size_t off = (((size_t)(b * Hn + hh) * Ln + l) << 6) + hd;
                    *(uint32_t*)(dst + off) =
                        pack2h(C[mi][ni][half*2] * s, C[mi][ni][half*2+1] * s);
                }
            }
    } else {
        #pragma unroll
        for (int mi = 0; mi < 4; mi++)
            #pragma unroll
            for (int ni = 0; ni < 4; ni++) {
                int row = row0 + wm * 64 + mi * 16 + (lane >> 2);
                int col = col0 + wn * 32 + ni * 8 + (lane & 3) * 2;
                float2 v0 = make_float2(C[mi][ni][0] * INV_OUT,
                                        C[mi][ni][1] * INV_OUT);
                float2 v1 = make_float2(C[mi][ni][2] * INV_OUT,
                                        C[mi][ni][3] * INV_OUT);
                *(float2*)(outp + (size_t)row * Dn + col) = v0;
                *(float2*)(outp + (size_t)(row + 8) * Dn + col) = v1;
            }
    }
}

// ---------------------------------------------------------------------------
// fp16 1-pass flash attention with LPT scheduling (qt reversed: heaviest
// CTAs dispatch first) and fine-grain causal block skips (warp-uniform;
// skipped blocks are exactly the fully-masked ones, so output is
// bit-identical: S init 0 -> mask -1e30 -> exp 0; P blocks skipped only
// when exactly 0).
// ---------------------------------------------------------------------------
constexpr int QS = 72;
constexpr int A_STAGE = 18432;
constexpr int ATTN_SMEM_BYTES = 55296;

__global__ void __launch_bounds__(256) attn_kernel()
{
    extern __shared__ uint16_t smh[];
    const uint32_t sb = s2u(smh);

    const int qt   = (int)gridDim.x - 1 - (int)blockIdx.x;   // LPT: big first
    const int h    = blockIdx.y;
    const int b    = blockIdx.z;
    const int tid  = threadIdx.x;
    const int lane = tid & 31;
    const int wid  = tid >> 5;
    const int r0   = wid * 16;

    const size_t base = ((size_t)(b * Hn + h) * Ln) * HDn;
    const uint16_t* q_g = g_q16 + base;
    const uint16_t* k_g = g_k16 + base;
    const uint16_t* v_g = g_v16 + base;

    // Stage Q tile [128][64] at elem offset 18432
    #pragma unroll
    for (int i = 0; i < 4; i++) {
        int idx = tid + i * 256;
        int r = idx >> 3, c8 = idx & 7;
        size_t go = (size_t)(qt * 128 + r) * HDn + c8 * 8;
        *(uint4*)(smh + 18432 + r * QS + c8 * 8) = *(const uint4*)(q_g + go);
    }

    const int ktmax = 2 * qt + 2;

    auto issue_kv = [&](int kt_, int s_) {
        uint32_t dstb = sb + (uint32_t)s_ * A_STAGE;
        #pragma unroll
        for (int i = 0; i < 4; i++) {
            int p = i >> 1;                    // 0 = K, 1 = V
            int local = (i & 1) * 256 + tid;
            int r = local >> 3, cc = local & 7;
            uint32_t dst = dstb + p * 9216u + (uint32_t)(r * QS + cc * 8) * 2;
            const uint16_t* gp = p ? v_g : k_g;
            cp16(dst, gp + (size_t)(kt_ * 64 + r) * HDn + cc * 8);
        }
    };
    issue_kv(0, 0);
    CP_COMMIT();
    __syncthreads();

    // Extract Q fragments to registers (reused every kt iteration)
    uint32_t qf[4][4];
    #pragma unroll
    for (int ks = 0; ks < 4; ks++) {
        uint32_t qaddr = sb + (uint32_t)((18432 + (r0 + (lane & 15)) * QS
                          + ks * 16 + ((lane >> 4) * 8)) * 2);
        ldm_x4(qf[ks], qaddr);
    }

    float m0 = -1e30f, m1 = -1e30f, l0 = 0.f, l1 = 0.f;
    float O[8][4];
    #pragma unroll
    for (int nt = 0; nt < 8; nt++)
        #pragma unroll
        for (int q = 0; q < 4; q++) O[nt][q] = 0.f;

    const int qbase = qt * 128 + r0;

    for (int kt = 0; kt < ktmax; kt++) {
        CP_WAIT0();
        __syncthreads();
        if (kt + 1 < ktmax) {
            issue_kv(kt + 1, (kt + 1) & 1);
            CP_COMMIT();
        }

        if (kt * 64 > qbase + 15) continue;

        const uint32_t stgb = sb + (uint32_t)(kt & 1) * A_STAGE;
        // Highest key offset (within tile) this warp can see unmasked
        const int kmax = qbase + 15 - kt * 64;   // >= 0 here

        // ---- S = Q * K^T (skip fully-masked 16-key blocks) ----
        float S[8][4];
        #pragma unroll
        for (int nt = 0; nt < 8; nt++)
            #pragma unroll
            for (int q = 0; q < 4; q++) S[nt][q] = 0.f;

        #pragma unroll
        for (int ntp = 0; ntp < 4; ntp++) {
            if (ntp * 16 > kmax) break;        // warp-uniform
            #pragma unroll
            for (int ks = 0; ks < 4; ks++) {
                uint32_t kaddr = stgb + (uint32_t)(((ntp * 16 + (lane & 7)
                                  + ((lane >> 4) << 3)) * QS
                                  + ((lane >> 3) & 1) * 8 + ks * 16) * 2);
                uint32_t bh[4];
                ldm_x4(bh, kaddr);
                mma_f16(S[2*ntp],   qf[ks], bh);
                mma_f16(S[2*ntp+1], qf[ks], bh + 2);
            }
        }

        // ---- causal mask (diagonal tiles only) ----
        if (kt * 64 + 63 > qbase) {
            int q0 = qbase + (lane >> 2);
            int q1 = q0 + 8;
            #pragma unroll
            for (int nt = 0; nt < 8; nt++) {
                int k0 = kt * 64 + nt * 8 + (lane & 3) * 2;
                if (k0     > q0) S[nt][0] = -1e30f;
                if (k0 + 1 > q0) S[nt][1] = -1e30f;
                if (k0     > q1) S[nt][2] = -1e30f;
                if (k0 + 1 > q1) S[nt][3] = -1e30f;
            }
        }

        // ---- online softmax ----
        float mx0 = -1e30f, mx1 = -1e30f;
        #pragma unroll
        for (int nt = 0; nt < 8; nt++) {
            mx0 = fmaxf(mx0, fmaxf(S[nt][0], S[nt][1]));
            mx1 = fmaxf(mx1, fmaxf(S[nt][2], S[nt][3]));
        }
        mx0 = fmaxf(mx0, __shfl_xor_sync(0xffffffffu, mx0, 1));
        mx0 = fmaxf(mx0, __shfl_xor_sync(0xffffffffu, mx0, 2));
        mx1 = fmaxf(mx1, __shfl_xor_sync(0xffffffffu, mx1, 1));
        mx1 = fmaxf(mx1, __shfl_xor_sync(0xffffffffu, mx1, 2));
        float nm0 = fmaxf(m0, mx0), nm1 = fmaxf(m1, mx1);
        float c0 = __expf(m0 - nm0), c1 = __expf(m1 - nm1);
        float s0 = 0.f, s1 = 0.f;
        #pragma unroll
        for (int nt = 0; nt < 8; nt++) {
            S[nt][0] = __expf(S[nt][0] - nm0);
            S[nt][1] = __expf(S[nt][1] - nm0);
            S[nt][2] = __expf(S[nt][2] - nm1);
            S[nt][3] = __expf(S[nt][3] - nm1);
            s0 += S[nt][0] + S[nt][1];
            s1 += S[nt][2] + S[nt][3];
        }
        s0 += __shfl_xor_sync(0xffffffffu, s0, 1);
        s0 += __shfl_xor_sync(0xffffffffu, s0, 2);
        s1 += __shfl_xor_sync(0xffffffffu, s1, 1);
        s1 += __shfl_xor_sync(0xffffffffu, s1, 2);
        m0 = nm0; m1 = nm1;
        l0 = l0 * c0 + s0;
        l1 = l1 * c1 + s1;
        #pragma unroll
        for (int nt = 0; nt < 8; nt++) {
            O[nt][0] *= c0; O[nt][1] *= c0;
            O[nt][2] *= c1; O[nt][3] *= c1;
        }

        // ---- O += P * V (skip g-blocks whose P is exactly 0) ----
        #pragma unroll
        for (int g = 0; g < 4; g++) {
            if (g * 16 > kmax) break;          // warp-uniform; P == 0 there
            uint32_t ah[4];
            ah[0] = pack2h(S[2*g][0],   S[2*g][1]);
            ah[1] = pack2h(S[2*g][2],   S[2*g][3]);
            ah[2] = pack2h(S[2*g+1][0], S[2*g+1][1]);
            ah[3] = pack2h(S[2*g+1][2], S[2*g+1][3]);
            #pragma unroll
            for (int ntp = 0; ntp < 4; ntp++) {
                uint32_t vaddr = stgb + 9216u
                    + (uint32_t)(((g * 16 + (lane & 15)) * QS
                                  + ntp * 16 + ((lane >> 4) << 3)) * 2);
                uint32_t vh[4];
                ldm_x4t(vh, vaddr);
                mma_f16(O[2*ntp],   ah, vh);
                mma_f16(O[2*ntp+1], ah, vh + 2);
            }
        }
    }

    // Finalize: scale by SC_Y/l, store y as single fp16 for out-proj
    float il0 = SC_Y / l0, il1 = SC_Y / l1;
    int rowg = qt * 128 + r0 + (lane >> 2);
    #pragma unroll
    for (int nt = 0; nt < 8; nt++) {
        int hd = nt * 8 + (lane & 3) * 2;
        size_t o0 = (size_t)(b * Ln + rowg) * Dn + h * 64 + hd;
        size_t o1 = (size_t)(b * Ln + rowg + 8) * Dn + h * 64 + hd;
        *(uint32_t*)(g_y16 + o0) = pack2h(O[nt][0] * il0, O[nt][1] * il0);
        *(uint32_t*)(g_y16 + o1) = pack2h(O[nt][2] * il1, O[nt][3] * il1);
    }
}

// ---------------------------------------------------------------------------
extern "C" void kernel_launch(void* const* d_in, const int* in_sizes, int n_in,
                              void* d_out, int out_size)
{
    (void)in_sizes; (void)n_in; (void)out_size;
    const float* x  = (const float*)d_in[0];
    const float* Wq = (const float*)d_in[1];
    const float* Wk = (const float*)d_in[2];
    const float* Wv = (const float*)d_in[3];
    const float* Wo = (const float*)d_in[4];
    float* out = (float*)d_out;

    cudaFuncSetAttribute(gemm_mma_kernel,
                         cudaFuncAttributeMaxDynamicSharedMemorySize,
                         GEMM_SMEM_BYTES);
    cudaFuncSetAttribute(attn_kernel,
                         cudaFuncAttributeMaxDynamicSharedMemorySize,
                         ATTN_SMEM_BYTES);

    prep_kernel<<<8192, 256>>>(x, Wq, Wk, Wv, Wo);
    gemm_mma_kernel<<<dim3(Dn/128, NROW/128, 3), 256, GEMM_SMEM_BYTES>>>(nullptr, 0);
    attn_kernel<<<dim3(Ln/128, Hn, Bn), 256, ATTN_SMEM_BYTES>>>();
    gemm_mma_kernel<<<dim3(Dn/128, NROW/128, 1), 256, GEMM_SMEM_BYTES>>>(out, 1);
}

// round 16
// speedup vs baseline: 1.0090x; 1.0090x over previous
#include <cuda_runtime.h>
#include <cuda_bf16.h>
#include <cuda_fp16.h>
#include <cstdint>

// Problem constants
constexpr int Bn  = 2;
constexpr int Ln  = 2048;
constexpr int Dn  = 1024;
constexpr int Hn  = 16;
constexpr int HDn = 64;
constexpr int NROW = Bn * Ln;   // 4096
constexpr size_t PLANE = (size_t)Bn * Hn * Ln * HDn;  // 4M elems

// Scaling
constexpr float SC_X = 16.f;
constexpr float SC_W = 32.f;
constexpr float SC_Y = 256.f;
constexpr float INV_QKV = 1.f / (16.f * 32.f);    // 1/512
constexpr float INV_OUT = 1.f / (256.f * 32.f);   // 1/8192

// Scratch (device globals: allocation-free)
__device__ uint16_t g_x16[(size_t)NROW * Dn];     // fp16 of 16*x, [m][k]
__device__ uint16_t g_w16[(size_t)4 * Dn * Dn];   // fp16(32W): Wq,Wk,Wv,Wo [k][n]
__device__ uint16_t g_q16[PLANE];                 // fp16 of 0.5*q, [B,H,L,HD]
__device__ uint16_t g_k16[PLANE];                 // fp16 of 0.25*k
__device__ uint16_t g_v16[PLANE];                 // fp16 of v
__device__ uint16_t g_y16[(size_t)NROW * Dn];     // fp16 of 256*y

// ---------------------------------------------------------------------------
// Helpers
// ---------------------------------------------------------------------------
__device__ __forceinline__ uint32_t s2u(const void* p) {
    uint32_t a;
    asm("{ .reg .u64 t; cvta.to.shared.u64 t, %1; cvt.u32.u64 %0, t; }"
        : "=r"(a) : "l"(p));
    return a;
}
__device__ __forceinline__ void cp16(uint32_t dst, const void* src) {
    asm volatile("cp.async.cg.shared.global [%0], [%1], 16;"
                 :: "r"(dst), "l"(src) : "memory");
}
#define CP_COMMIT() asm volatile("cp.async.commit_group;" ::: "memory")
#define CP_WAIT0()  asm volatile("cp.async.wait_group 0;" ::: "memory")

__device__ __forceinline__ void ldm_x4(uint32_t* r, uint32_t a) {
    asm volatile("ldmatrix.sync.aligned.m8n8.x4.shared.b16 {%0,%1,%2,%3}, [%4];"
                 : "=r"(r[0]), "=r"(r[1]), "=r"(r[2]), "=r"(r[3]) : "r"(a));
}
__device__ __forceinline__ void ldm_x4t(uint32_t* r, uint32_t a) {
    asm volatile("ldmatrix.sync.aligned.m8n8.x4.trans.shared.b16 {%0,%1,%2,%3}, [%4];"
                 : "=r"(r[0]), "=r"(r[1]), "=r"(r[2]), "=r"(r[3]) : "r"(a));
}
__device__ __forceinline__ void mma_f16(float* c, const uint32_t* a,
                                        const uint32_t* b) {
    asm volatile(
        "mma.sync.aligned.m16n8k16.row.col.f32.f16.f16.f32 "
        "{%0,%1,%2,%3}, {%4,%5,%6,%7}, {%8,%9}, {%0,%1,%2,%3};"
        : "+f"(c[0]), "+f"(c[1]), "+f"(c[2]), "+f"(c[3])
        : "r"(a[0]), "r"(a[1]), "r"(a[2]), "r"(a[3]), "r"(b[0]), "r"(b[1]));
}
// fp16 helpers
__device__ __forceinline__ uint16_t hfu(float f) {
    __half h = __float2half_rn(f);
    return *(uint16_t*)&h;
}
__device__ __forceinline__ uint2 pack4h(float4 v) {
    uint16_t h0 = hfu(v.x), h1 = hfu(v.y), h2 = hfu(v.z), h3 = hfu(v.w);
    return make_uint2((uint32_t)h0 | ((uint32_t)h1 << 16),
                      (uint32_t)h2 | ((uint32_t)h3 << 16));
}
__device__ __forceinline__ uint32_t pack2h(float f0, float f1) {
    return (uint32_t)hfu(f0) | ((uint32_t)hfu(f1) << 16);
}

// ---------------------------------------------------------------------------
// Prep: x -> fp16(16x) single [m][k]; all 4 weights -> fp16(32W) [k][n].
// ---------------------------------------------------------------------------
__global__ void __launch_bounds__(256) prep_kernel(
    const float* __restrict__ x,
    const float* __restrict__ Wq, const float* __restrict__ Wk,
    const float* __restrict__ Wv, const float* __restrict__ Wo)
{
    int i = blockIdx.x * 256 + threadIdx.x;   // float4 index
    if (i < (1 << 20)) {
        float4 v = ((const float4*)x)[i];
        v.x *= SC_X; v.y *= SC_X; v.z *= SC_X; v.w *= SC_X;
        ((uint2*)g_x16)[i] = pack4h(v);
    } else {
        int j = i - (1 << 20);
        int slot = j >> 18;
        int off  = j & ((1 << 18) - 1);
        const float* w = (slot == 0) ? Wq : (slot == 1) ? Wk
                        : (slot == 2) ? Wv : Wo;
        float4 v = ((const float4*)w)[off];
        v.x *= SC_W; v.y *= SC_W; v.z *= SC_W; v.w *= SC_W;
        ((uint2*)g_w16)[((size_t)slot << 18) + off] = pack4h(v);
    }
}

// ---------------------------------------------------------------------------
// fp16 1-pass GEMM v2 (unchanged from round 14): 128x128 CTA, 8 warps (2m x 4n),
// warp tile 64x32, BK=64, 2-stage cp.async.
// Stage (bytes): A [0,18432) 128x144B; B [18432,35840) 64x272B. 2 CTAs/SM.
// ---------------------------------------------------------------------------
constexpr int G_STAGE = 35840;
constexpr int GEMM_SMEM_BYTES = 2 * G_STAGE;   // 71680

__global__ void __launch_bounds__(256, 2) gemm_mma_kernel(
    float* __restrict__ outp, int mode)
{
    extern __shared__ uint16_t smg[];
    const uint32_t sb = s2u(smg);

    const int tid  = threadIdx.x;
    const int lane = tid & 31;
    const int w    = tid >> 5;
    const int wm   = w >> 2;
    const int wn   = w & 3;
    const int col0 = blockIdx.x * 128;
    const int row0 = blockIdx.y * 128;
    const int z    = blockIdx.z;

    const uint16_t* Ap = (mode == 0) ? g_x16 : g_y16;
    const int slot = (mode == 0) ? z : 3;
    const uint16_t* Bp = g_w16 + ((size_t)slot << 20);

    float C[4][4][4];
    #pragma unroll
    for (int mi = 0; mi < 4; mi++)
        #pragma unroll
        for (int ni = 0; ni < 4; ni++)
            #pragma unroll
            for (int q = 0; q < 4; q++) C[mi][ni][q] = 0.f;

    auto issue = [&](int c_, int s_) {
        uint32_t dstb = sb + (uint32_t)s_ * G_STAGE;
        int k0 = c_ * 64;
        #pragma unroll
        for (int i = 0; i < 4; i++) {
            int local = i * 256 + tid;
            int r = local >> 3, cc = local & 7;
            uint32_t dst = dstb + (uint32_t)(r * 144 + cc * 16);
            cp16(dst, Ap + (size_t)(row0 + r) * Dn + k0 + cc * 8);
        }
        #pragma unroll
        for (int i = 0; i < 4; i++) {
            int local = i * 256 + tid;
            int kk = local >> 4, cc = local & 15;
            uint32_t dst = dstb + 18432u + (uint32_t)(kk * 272 + cc * 16);
            cp16(dst, Bp + (size_t)(k0 + kk) * Dn + col0 + cc * 8);
        }
    };

    issue(0, 0);
    CP_COMMIT();

    for (int c = 0; c < 16; c++) {
        CP_WAIT0();
        __syncthreads();
        if (c + 1 < 16) {
            issue(c + 1, (c + 1) & 1);
            CP_COMMIT();
        }
        const uint32_t stgb = sb + (uint32_t)(c & 1) * G_STAGE;

        #pragma unroll
        for (int ks = 0; ks < 4; ks++) {
            uint32_t af[4][4], bf[4][2];
            #pragma unroll
            for (int mi = 0; mi < 4; mi++) {
                uint32_t off = (uint32_t)((wm * 64 + mi * 16 + (lane & 15)) * 144
                                          + ks * 32 + ((lane >> 4) * 16));
                ldm_x4(af[mi], stgb + off);
            }
            #pragma unroll
            for (int g = 0; g < 2; g++) {
                uint32_t off = 18432u
                    + (uint32_t)((ks * 16 + (lane & 15)) * 272
                                 + (wn * 32 + g * 16 + ((lane >> 4) * 8)) * 2);
                uint32_t t[4];
                ldm_x4t(t, stgb + off);
                bf[g*2][0]   = t[0]; bf[g*2][1]   = t[1];
                bf[g*2+1][0] = t[2]; bf[g*2+1][1] = t[3];
            }
            #pragma unroll
            for (int mi = 0; mi < 4; mi++)
                #pragma unroll
                for (int ni = 0; ni < 4; ni++)
                    mma_f16(C[mi][ni], af[mi], bf[ni]);
        }
        __syncthreads();
    }

    if (mode == 0) {
        const float s = INV_QKV * ((z == 0) ? 0.5f : (z == 1) ? 0.25f : 1.f);
        uint16_t* dst = (z == 0) ? g_q16 : (z == 1) ? g_k16 : g_v16;
        #pragma unroll
        for (int mi = 0; mi < 4; mi++)
            #pragma unroll
            for (int ni = 0; ni < 4; ni++) {
                int row = row0 + wm * 64 + mi * 16 + (lane >> 2);
                int col = col0 + wn * 32 + ni * 8 + (lane & 3) * 2;
                int hh = col >> 6, hd = col & 63;
                #pragma unroll
                for (int half = 0; half < 2; half++) {
                    int r = row + half * 8;
                    int b = r >> 11, l = r & 2047;
                    size_t off = (((size_t)(b * Hn + hh) * Ln + l) << 6) + hd;
                    *(uint32_t*)(dst + off) =
                        pack2h(C[mi][ni][half*2] * s, C[mi][ni][half*2+1] * s);
                }
            }
    } else {
        #pragma unroll
        for (int mi = 0; mi < 4; mi++)
            #pragma unroll
            for (int ni = 0; ni < 4; ni++) {
                int row = row0 + wm * 64 + mi * 16 + (lane >> 2);
                int col = col0 + wn * 32 + ni * 8 + (lane & 3) * 2;
                float2 v0 = make_float2(C[mi][ni][0] * INV_OUT,
                                        C[mi][ni][1] * INV_OUT);
                float2 v1 = make_float2(C[mi][ni][2] * INV_OUT,
                                        C[mi][ni][3] * INV_OUT);
                *(float2*)(outp + (size_t)row * Dn + col) = v0;
                *(float2*)(outp + (size_t)(row + 8) * Dn + col) = v1;
            }
    }
}

// ---------------------------------------------------------------------------
// fp16 1-pass flash attention (round-14 body; linear qt). Causal block skips
// re-added as PER-BLOCK warp-uniform `if` guards (no break -> unrolling
// preserved). Skipped blocks are exactly the fully-masked ones, so output is
// bit-identical (S init 0 -> mask -1e30 -> exp 0; P blocks skipped only when
// exactly 0).
// ---------------------------------------------------------------------------
constexpr int QS = 72;
constexpr int A_STAGE = 18432;
constexpr int ATTN_SMEM_BYTES = 55296;

__global__ void __launch_bounds__(256) attn_kernel()
{
    extern __shared__ uint16_t smh[];
    const uint32_t sb = s2u(smh);

    const int qt   = blockIdx.x;
    const int h    = blockIdx.y;
    const int b    = blockIdx.z;
    const int tid  = threadIdx.x;
    const int lane = tid & 31;
    const int wid  = tid >> 5;
    const int r0   = wid * 16;

    const size_t base = ((size_t)(b * Hn + h) * Ln) * HDn;
    const uint16_t* q_g = g_q16 + base;
    const uint16_t* k_g = g_k16 + base;
    const uint16_t* v_g = g_v16 + base;

    // Stage Q tile [128][64] at elem offset 18432
    #pragma unroll
    for (int i = 0; i < 4; i++) {
        int idx = tid + i * 256;
        int r = idx >> 3, c8 = idx & 7;
        size_t go = (size_t)(qt * 128 + r) * HDn + c8 * 8;
        *(uint4*)(smh + 18432 + r * QS + c8 * 8) = *(const uint4*)(q_g + go);
    }

    const int ktmax = 2 * qt + 2;

    auto issue_kv = [&](int kt_, int s_) {
        uint32_t dstb = sb + (uint32_t)s_ * A_STAGE;
        #pragma unroll
        for (int i = 0; i < 4; i++) {
            int p = i >> 1;                    // 0 = K, 1 = V
            int local = (i & 1) * 256 + tid;
            int r = local >> 3, cc = local & 7;
            uint32_t dst = dstb + p * 9216u + (uint32_t)(r * QS + cc * 8) * 2;
            const uint16_t* gp = p ? v_g : k_g;
            cp16(dst, gp + (size_t)(kt_ * 64 + r) * HDn + cc * 8);
        }
    };
    issue_kv(0, 0);
    CP_COMMIT();
    __syncthreads();

    // Extract Q fragments to registers (reused every kt iteration)
    uint32_t qf[4][4];
    #pragma unroll
    for (int ks = 0; ks < 4; ks++) {
        uint32_t qaddr = sb + (uint32_t)((18432 + (r0 + (lane & 15)) * QS
                          + ks * 16 + ((lane >> 4) * 8)) * 2);
        ldm_x4(qf[ks], qaddr);
    }

    float m0 = -1e30f, m1 = -1e30f, l0 = 0.f, l1 = 0.f;
    float O[8][4];
    #pragma unroll
    for (int nt = 0; nt < 8; nt++)
        #pragma unroll
        for (int q = 0; q < 4; q++) O[nt][q] = 0.f;

    const int qbase = qt * 128 + r0;

    for (int kt = 0; kt < ktmax; kt++) {
        CP_WAIT0();
        __syncthreads();
        if (kt + 1 < ktmax) {
            issue_kv(kt + 1, (kt + 1) & 1);
            CP_COMMIT();
        }

        if (kt * 64 > qbase + 15) continue;

        const uint32_t stgb = sb + (uint32_t)(kt & 1) * A_STAGE;
        // Highest key offset (within tile) this warp can see unmasked (>= 0)
        const int kmax = qbase + 15 - kt * 64;

        // ---- S = Q * K^T (per-block guards; unrolling preserved) ----
        float S[8][4];
        #pragma unroll
        for (int nt = 0; nt < 8; nt++)
            #pragma unroll
            for (int q = 0; q < 4; q++) S[nt][q] = 0.f;

        #pragma unroll
        for (int ntp = 0; ntp < 4; ntp++) {
            if (ntp * 16 <= kmax) {            // warp-uniform guard
                #pragma unroll
                for (int ks = 0; ks < 4; ks++) {
                    uint32_t kaddr = stgb + (uint32_t)(((ntp * 16 + (lane & 7)
                                      + ((lane >> 4) << 3)) * QS
                                      + ((lane >> 3) & 1) * 8 + ks * 16) * 2);
                    uint32_t bh[4];
                    ldm_x4(bh, kaddr);
                    mma_f16(S[2*ntp],   qf[ks], bh);
                    mma_f16(S[2*ntp+1], qf[ks], bh + 2);
                }
            }
        }

        // ---- causal mask (diagonal tiles only) ----
        if (kt * 64 + 63 > qbase) {
            int q0 = qbase + (lane >> 2);
            int q1 = q0 + 8;
            #pragma unroll
            for (int nt = 0; nt < 8; nt++) {
                int k0 = kt * 64 + nt * 8 + (lane & 3) * 2;
                if (k0     > q0) S[nt][0] = -1e30f;
                if (k0 + 1 > q0) S[nt][1] = -1e30f;
                if (k0     > q1) S[nt][2] = -1e30f;
                if (k0 + 1 > q1) S[nt][3] = -1e30f;
            }
        }

        // ---- online softmax ----
        float mx0 = -1e30f, mx1 = -1e30f;
        #pragma unroll
        for (int nt = 0; nt < 8; nt++) {
            mx0 = fmaxf(mx0, fmaxf(S[nt][0], S[nt][1]));
            mx1 = fmaxf(mx1, fmaxf(S[nt][2], S[nt][3]));
        }
        mx0 = fmaxf(mx0, __shfl_xor_sync(0xffffffffu, mx0, 1));
        mx0 = fmaxf(mx0, __shfl_xor_sync(0xffffffffu, mx0, 2));
        mx1 = fmaxf(mx1, __shfl_xor_sync(0xffffffffu, mx1, 1));
        mx1 = fmaxf(mx1, __shfl_xor_sync(0xffffffffu, mx1, 2));
        float nm0 = fmaxf(m0, mx0), nm1 = fmaxf(m1, mx1);
        float c0 = __expf(m0 - nm0), c1 = __expf(m1 - nm1);
        float s0 = 0.f, s1 = 0.f;
        #pragma unroll
        for (int nt = 0; nt < 8; nt++) {
            S[nt][0] = __expf(S[nt][0] - nm0);
            S[nt][1] = __expf(S[nt][1] - nm0);
            S[nt][2] = __expf(S[nt][2] - nm1);
            S[nt][3] = __expf(S[nt][3] - nm1);
            s0 += S[nt][0] + S[nt][1];
            s1 += S[nt][2] + S[nt][3];
        }
        s0 += __shfl_xor_sync(0xffffffffu, s0, 1);
        s0 += __shfl_xor_sync(0xffffffffu, s0, 2);
        s1 += __shfl_xor_sync(0xffffffffu, s1, 1);
        s1 += __shfl_xor_sync(0xffffffffu, s1, 2);
        m0 = nm0; m1 = nm1;
        l0 = l0 * c0 + s0;
        l1 = l1 * c1 + s1;
        #pragma unroll
        for (int nt = 0; nt < 8; nt++) {
            O[nt][0] *= c0; O[nt][1] *= c0;
            O[nt][2] *= c1; O[nt][3] *= c1;
        }

        // ---- O += P * V (per-block guards; P == 0 on skipped blocks) ----
        #pragma unroll
        for (int g = 0; g < 4; g++) {
            if (g * 16 <= kmax) {              // warp-uniform guard
                uint32_t ah[4];
                ah[0] = pack2h(S[2*g][0],   S[2*g][1]);
                ah[1] = pack2h(S[2*g][2],   S[2*g][3]);
                ah[2] = pack2h(S[2*g+1][0], S[2*g+1][1]);
                ah[3] = pack2h(S[2*g+1][2], S[2*g+1][3]);
                #pragma unroll
                for (int ntp = 0; ntp < 4; ntp++) {
                    uint32_t vaddr = stgb + 9216u
                        + (uint32_t)(((g * 16 + (lane & 15)) * QS
                                      + ntp * 16 + ((lane >> 4) << 3)) * 2);
                    uint32_t vh[4];
                    ldm_x4t(vh, vaddr);
                    mma_f16(O[2*ntp],   ah, vh);
                    mma_f16(O[2*ntp+1], ah, vh + 2);
                }
            }
        }
    }

    // Finalize: scale by SC_Y/l, store y as single fp16 for out-proj
    float il0 = SC_Y / l0, il1 = SC_Y / l1;
    int rowg = qt * 128 + r0 + (lane >> 2);
    #pragma unroll
    for (int nt = 0; nt < 8; nt++) {
        int hd = nt * 8 + (lane & 3) * 2;
        size_t o0 = (size_t)(b * Ln + rowg) * Dn + h * 64 + hd;
        size_t o1 = (size_t)(b * Ln + rowg + 8) * Dn + h * 64 + hd;
        *(uint32_t*)(g_y16 + o0) = pack2h(O[nt][0] * il0, O[nt][1] * il0);
        *(uint32_t*)(g_y16 + o1) = pack2h(O[nt][2] * il1, O[nt][3] * il1);
    }
}

// ---------------------------------------------------------------------------
extern "C" void kernel_launch(void* const* d_in, const int* in_sizes, int n_in,
                              void* d_out, int out_size)
{
    (void)in_sizes; (void)n_in; (void)out_size;
    const float* x  = (const float*)d_in[0];
    const float* Wq = (const float*)d_in[1];
    const float* Wk = (const float*)d_in[2];
    const float* Wv = (const float*)d_in[3];
    const float* Wo = (const float*)d_in[4];
    float* out = (float*)d_out;

    cudaFuncSetAttribute(gemm_mma_kernel,
                         cudaFuncAttributeMaxDynamicSharedMemorySize,
                         GEMM_SMEM_BYTES);
    cudaFuncSetAttribute(attn_kernel,
                         cudaFuncAttributeMaxDynamicSharedMemorySize,
                         ATTN_SMEM_BYTES);

    prep_kernel<<<8192, 256>>>(x, Wq, Wk, Wv, Wo);
    gemm_mma_kernel<<<dim3(Dn/128, NROW/128, 3), 256, GEMM_SMEM_BYTES>>>(nullptr, 0);
    attn_kernel<<<dim3(Ln/128, Hn, Bn), 256, ATTN_SMEM_BYTES>>>();
    gemm_mma_kernel<<<dim3(Dn/128, NROW/128, 1), 256, GEMM_SMEM_BYTES>>>(out, 1);
}

// round 17
// speedup vs baseline: 1.0601x; 1.0507x over previous
#include <cuda_runtime.h>
#include <cuda_bf16.h>
#include <cuda_fp16.h>
#include <cstdint>

// Problem constants
constexpr int Bn  = 2;
constexpr int Ln  = 2048;
constexpr int Dn  = 1024;
constexpr int Hn  = 16;
constexpr int HDn = 64;
constexpr int NROW = Bn * Ln;   // 4096
constexpr size_t PLANE = (size_t)Bn * Hn * Ln * HDn;  // 4M elems

// Scaling
constexpr float SC_X = 16.f;
constexpr float SC_W = 32.f;
constexpr float SC_Y = 256.f;
constexpr float INV_QKV = 1.f / (16.f * 32.f);    // 1/512
constexpr float INV_OUT = 1.f / (256.f * 32.f);   // 1/8192

// Scratch (device globals: allocation-free)
__device__ uint16_t g_x16[(size_t)NROW * Dn];     // fp16 of 16*x, [m][k]
__device__ uint16_t g_w16[(size_t)4 * Dn * Dn];   // fp16(32W): Wq,Wk,Wv,Wo [k][n]
__device__ uint16_t g_q16[PLANE];                 // fp16 of 0.5*q, [B,H,L,HD]
__device__ uint16_t g_k16[PLANE];                 // fp16 of 0.25*k
__device__ uint16_t g_v16[PLANE];                 // fp16 of v
__device__ uint16_t g_y16[(size_t)NROW * Dn];     // fp16 of 256*y

// ---------------------------------------------------------------------------
// Helpers
// ---------------------------------------------------------------------------
__device__ __forceinline__ uint32_t s2u(const void* p) {
    uint32_t a;
    asm("{ .reg .u64 t; cvta.to.shared.u64 t, %1; cvt.u32.u64 %0, t; }"
        : "=r"(a) : "l"(p));
    return a;
}
__device__ __forceinline__ void cp16(uint32_t dst, const void* src) {
    asm volatile("cp.async.cg.shared.global [%0], [%1], 16;"
                 :: "r"(dst), "l"(src) : "memory");
}
#define CP_COMMIT() asm volatile("cp.async.commit_group;" ::: "memory")
#define CP_WAIT0()  asm volatile("cp.async.wait_group 0;" ::: "memory")

__device__ __forceinline__ void ldm_x4(uint32_t* r, uint32_t a) {
    asm volatile("ldmatrix.sync.aligned.m8n8.x4.shared.b16 {%0,%1,%2,%3}, [%4];"
                 : "=r"(r[0]), "=r"(r[1]), "=r"(r[2]), "=r"(r[3]) : "r"(a));
}
__device__ __forceinline__ void ldm_x4t(uint32_t* r, uint32_t a) {
    asm volatile("ldmatrix.sync.aligned.m8n8.x4.trans.shared.b16 {%0,%1,%2,%3}, [%4];"
                 : "=r"(r[0]), "=r"(r[1]), "=r"(r[2]), "=r"(r[3]) : "r"(a));
}
__device__ __forceinline__ void mma_f16(float* c, const uint32_t* a,
                                        const uint32_t* b) {
    asm volatile(
        "mma.sync.aligned.m16n8k16.row.col.f32.f16.f16.f32 "
        "{%0,%1,%2,%3}, {%4,%5,%6,%7}, {%8,%9}, {%0,%1,%2,%3};"
        : "+f"(c[0]), "+f"(c[1]), "+f"(c[2]), "+f"(c[3])
        : "r"(a[0]), "r"(a[1]), "r"(a[2]), "r"(a[3]), "r"(b[0]), "r"(b[1]));
}
// fp16 helpers
__device__ __forceinline__ uint16_t hfu(float f) {
    __half h = __float2half_rn(f);
    return *(uint16_t*)&h;
}
__device__ __forceinline__ uint2 pack4h(float4 v) {
    uint16_t h0 = hfu(v.x), h1 = hfu(v.y), h2 = hfu(v.z), h3 = hfu(v.w);
    return make_uint2((uint32_t)h0 | ((uint32_t)h1 << 16),
                      (uint32_t)h2 | ((uint32_t)h3 << 16));
}
__device__ __forceinline__ uint32_t pack2h(float f0, float f1) {
    return (uint32_t)hfu(f0) | ((uint32_t)hfu(f1) << 16);
}

// ---------------------------------------------------------------------------
// Prep: x -> fp16(16x) single [m][k]; all 4 weights -> fp16(32W) [k][n].
// ---------------------------------------------------------------------------
__global__ void __launch_bounds__(256) prep_kernel(
    const float* __restrict__ x,
    const float* __restrict__ Wq, const float* __restrict__ Wk,
    const float* __restrict__ Wv, const float* __restrict__ Wo)
{
    int i = blockIdx.x * 256 + threadIdx.x;   // float4 index
    if (i < (1 << 20)) {
        float4 v = ((const float4*)x)[i];
        v.x *= SC_X; v.y *= SC_X; v.z *= SC_X; v.w *= SC_X;
        ((uint2*)g_x16)[i] = pack4h(v);
    } else {
        int j = i - (1 << 20);
        int slot = j >> 18;
        int off  = j & ((1 << 18) - 1);
        const float* w = (slot == 0) ? Wq : (slot == 1) ? Wk
                        : (slot == 2) ? Wv : Wo;
        float4 v = ((const float4*)w)[off];
        v.x *= SC_W; v.y *= SC_W; v.z *= SC_W; v.w *= SC_W;
        ((uint2*)g_w16)[((size_t)slot << 18) + off] = pack4h(v);
    }
}

// ---------------------------------------------------------------------------
// fp16 1-pass GEMM v3: 128x128 CTA, 8 warps (2m x 4n), warp tile 64x32,
// BK=64, 2-stage cp.async, ONE barrier per chunk (trailing barrier removed:
// the overwrite of stage c&1 happens at issue(c+2), which is ordered after
// the top-of-loop barrier of iteration c+1 where all warps have finished
// compute(c)).
// Stage (bytes): A [0,18432) 128x144B; B [18432,35840) 64x272B. 2 CTAs/SM.
// ---------------------------------------------------------------------------
constexpr int G_STAGE = 35840;
constexpr int GEMM_SMEM_BYTES = 2 * G_STAGE;   // 71680

__global__ void __launch_bounds__(256, 2) gemm_mma_kernel(
    float* __restrict__ outp, int mode)
{
    extern __shared__ uint16_t smg[];
    const uint32_t sb = s2u(smg);

    const int tid  = threadIdx.x;
    const int lane = tid & 31;
    const int w    = tid >> 5;
    const int wm   = w >> 2;
    const int wn   = w & 3;
    const int col0 = blockIdx.x * 128;
    const int row0 = blockIdx.y * 128;
    const int z    = blockIdx.z;

    const uint16_t* Ap = (mode == 0) ? g_x16 : g_y16;
    const int slot = (mode == 0) ? z : 3;
    const uint16_t* Bp = g_w16 + ((size_t)slot << 20);

    float C[4][4][4];
    #pragma unroll
    for (int mi = 0; mi < 4; mi++)
        #pragma unroll
        for (int ni = 0; ni < 4; ni++)
            #pragma unroll
            for (int q = 0; q < 4; q++) C[mi][ni][q] = 0.f;

    auto issue = [&](int c_, int s_) {
        uint32_t dstb = sb + (uint32_t)s_ * G_STAGE;
        int k0 = c_ * 64;
        #pragma unroll
        for (int i = 0; i < 4; i++) {
            int local = i * 256 + tid;
            int r = local >> 3, cc = local & 7;
            uint32_t dst = dstb + (uint32_t)(r * 144 + cc * 16);
            cp16(dst, Ap + (size_t)(row0 + r) * Dn + k0 + cc * 8);
        }
        #pragma unroll
        for (int i = 0; i < 4; i++) {
            int local = i * 256 + tid;
            int kk = local >> 4, cc = local & 15;
            uint32_t dst = dstb + 18432u + (uint32_t)(kk * 272 + cc * 16);
            cp16(dst, Bp + (size_t)(k0 + kk) * Dn + col0 + cc * 8);
        }
    };

    issue(0, 0);
    CP_COMMIT();

    for (int c = 0; c < 16; c++) {
        CP_WAIT0();
        __syncthreads();
        if (c + 1 < 16) {
            issue(c + 1, (c + 1) & 1);
            CP_COMMIT();
        }
        const uint32_t stgb = sb + (uint32_t)(c & 1) * G_STAGE;

        #pragma unroll
        for (int ks = 0; ks < 4; ks++) {
            uint32_t af[4][4], bf[4][2];
            #pragma unroll
            for (int mi = 0; mi < 4; mi++) {
                uint32_t off = (uint32_t)((wm * 64 + mi * 16 + (lane & 15)) * 144
                                          + ks * 32 + ((lane >> 4) * 16));
                ldm_x4(af[mi], stgb + off);
            }
            #pragma unroll
            for (int g = 0; g < 2; g++) {
                uint32_t off = 18432u
                    + (uint32_t)((ks * 16 + (lane & 15)) * 272
                                 + (wn * 32 + g * 16 + ((lane >> 4) * 8)) * 2);
                uint32_t t[4];
                ldm_x4t(t, stgb + off);
                bf[g*2][0]   = t[0]; bf[g*2][1]   = t[1];
                bf[g*2+1][0] = t[2]; bf[g*2+1][1] = t[3];
            }
            #pragma unroll
            for (int mi = 0; mi < 4; mi++)
                #pragma unroll
                for (int ni = 0; ni < 4; ni++)
                    mma_f16(C[mi][ni], af[mi], bf[ni]);
        }
        // no trailing barrier: next iteration's top barrier orders reuse
    }

    if (mode == 0) {
        const float s = INV_QKV * ((z == 0) ? 0.5f : (z == 1) ? 0.25f : 1.f);
        uint16_t* dst = (z == 0) ? g_q16 : (z == 1) ? g_k16 : g_v16;
        #pragma unroll
        for (int mi = 0; mi < 4; mi++)
            #pragma unroll
            for (int ni = 0; ni < 4; ni++) {
                int row = row0 + wm * 64 + mi * 16 + (lane >> 2);
                int col = col0 + wn * 32 + ni * 8 + (lane & 3) * 2;
                int hh = col >> 6, hd = col & 63;
                #pragma unroll
                for (int half = 0; half < 2; half++) {
                    int r = row + half * 8;
                    int b = r >> 11, l = r & 2047;
                    size_t off = (((size_t)(b * Hn + hh) * Ln + l) << 6) + hd;
                    *(uint32_t*)(dst + off) =
                        pack2h(C[mi][ni][half*2] * s, C[mi][ni][half*2+1] * s);
                }
            }
    } else {
        #pragma unroll
        for (int mi = 0; mi < 4; mi++)
            #pragma unroll
            for (int ni = 0; ni < 4; ni++) {
                int row = row0 + wm * 64 + mi * 16 + (lane >> 2);
                int col = col0 + wn * 32 + ni * 8 + (lane & 3) * 2;
                float2 v0 = make_float2(C[mi][ni][0] * INV_OUT,
                                        C[mi][ni][1] * INV_OUT);
                float2 v1 = make_float2(C[mi][ni][2] * INV_OUT,
                                        C[mi][ni][3] * INV_OUT);
                *(float2*)(outp + (size_t)row * Dn + col) = v0;
                *(float2*)(outp + (size_t)(row + 8) * Dn + col) = v1;
            }
    }
}

// ---------------------------------------------------------------------------
// fp16 1-pass flash attention (exact round-14 body, the 219.6 µs version).
// Q single fp16, register-resident; K,V single fp16, double-buffered via
// cp.async; P single-pass.
// ---------------------------------------------------------------------------
constexpr int QS = 72;
constexpr int A_STAGE = 18432;
constexpr int ATTN_SMEM_BYTES = 55296;

__global__ void __launch_bounds__(256) attn_kernel()
{
    extern __shared__ uint16_t smh[];
    const uint32_t sb = s2u(smh);

    const int qt   = blockIdx.x;
    const int h    = blockIdx.y;
    const int b    = blockIdx.z;
    const int tid  = threadIdx.x;
    const int lane = tid & 31;
    const int wid  = tid >> 5;
    const int r0   = wid * 16;

    const size_t base = ((size_t)(b * Hn + h) * Ln) * HDn;
    const uint16_t* q_g = g_q16 + base;
    const uint16_t* k_g = g_k16 + base;
    const uint16_t* v_g = g_v16 + base;

    // Stage Q tile [128][64] at elem offset 18432
    #pragma unroll
    for (int i = 0; i < 4; i++) {
        int idx = tid + i * 256;
        int r = idx >> 3, c8 = idx & 7;
        size_t go = (size_t)(qt * 128 + r) * HDn + c8 * 8;
        *(uint4*)(smh + 18432 + r * QS + c8 * 8) = *(const uint4*)(q_g + go);
    }

    const int ktmax = 2 * qt + 2;

    auto issue_kv = [&](int kt_, int s_) {
        uint32_t dstb = sb + (uint32_t)s_ * A_STAGE;
        #pragma unroll
        for (int i = 0; i < 4; i++) {
            int p = i >> 1;                    // 0 = K, 1 = V
            int local = (i & 1) * 256 + tid;
            int r = local >> 3, cc = local & 7;
            uint32_t dst = dstb + p * 9216u + (uint32_t)(r * QS + cc * 8) * 2;
            const uint16_t* gp = p ? v_g : k_g;
            cp16(dst, gp + (size_t)(kt_ * 64 + r) * HDn + cc * 8);
        }
    };
    issue_kv(0, 0);
    CP_COMMIT();
    __syncthreads();

    // Extract Q fragments to registers (reused every kt iteration)
    uint32_t qf[4][4];
    #pragma unroll
    for (int ks = 0; ks < 4; ks++) {
        uint32_t qaddr = sb + (uint32_t)((18432 + (r0 + (lane & 15)) * QS
                          + ks * 16 + ((lane >> 4) * 8)) * 2);
        ldm_x4(qf[ks], qaddr);
    }

    float m0 = -1e30f, m1 = -1e30f, l0 = 0.f, l1 = 0.f;
    float O[8][4];
    #pragma unroll
    for (int nt = 0; nt < 8; nt++)
        #pragma unroll
        for (int q = 0; q < 4; q++) O[nt][q] = 0.f;

    const int qbase = qt * 128 + r0;

    for (int kt = 0; kt < ktmax; kt++) {
        CP_WAIT0();
        __syncthreads();
        if (kt + 1 < ktmax) {
            issue_kv(kt + 1, (kt + 1) & 1);
            CP_COMMIT();
        }

        if (kt * 64 > qbase + 15) continue;

        const uint32_t stgb = sb + (uint32_t)(kt & 1) * A_STAGE;

        // ---- S = Q * K^T ----
        float S[8][4];
        #pragma unroll
        for (int nt = 0; nt < 8; nt++)
            #pragma unroll
            for (int q = 0; q < 4; q++) S[nt][q] = 0.f;

        #pragma unroll
        for (int ks = 0; ks < 4; ks++) {
            #pragma unroll
            for (int ntp = 0; ntp < 4; ntp++) {
                uint32_t kaddr = stgb + (uint32_t)(((ntp * 16 + (lane & 7)
                                  + ((lane >> 4) << 3)) * QS
                                  + ((lane >> 3) & 1) * 8 + ks * 16) * 2);
                uint32_t bh[4];
                ldm_x4(bh, kaddr);
                mma_f16(S[2*ntp],   qf[ks], bh);
                mma_f16(S[2*ntp+1], qf[ks], bh + 2);
            }
        }

        // ---- causal mask (diagonal tiles only) ----
        if (kt * 64 + 63 > qbase) {
            int q0 = qbase + (lane >> 2);
            int q1 = q0 + 8;
            #pragma unroll
            for (int nt = 0; nt < 8; nt++) {
                int k0 = kt * 64 + nt * 8 + (lane & 3) * 2;
                if (k0     > q0) S[nt][0] = -1e30f;
                if (k0 + 1 > q0) S[nt][1] = -1e30f;
                if (k0     > q1) S[nt][2] = -1e30f;
                if (k0 + 1 > q1) S[nt][3] = -1e30f;
            }
        }

        // ---- online softmax ----
        float mx0 = -1e30f, mx1 = -1e30f;
        #pragma unroll
        for (int nt = 0; nt < 8; nt++) {
            mx0 = fmaxf(mx0, fmaxf(S[nt][0], S[nt][1]));
            mx1 = fmaxf(mx1, fmaxf(S[nt][2], S[nt][3]));
        }
        mx0 = fmaxf(mx0, __shfl_xor_sync(0xffffffffu, mx0, 1));
        mx0 = fmaxf(mx0, __shfl_xor_sync(0xffffffffu, mx0, 2));
        mx1 = fmaxf(mx1, __shfl_xor_sync(0xffffffffu, mx1, 1));
        mx1 = fmaxf(mx1, __shfl_xor_sync(0xffffffffu, mx1, 2));
        float nm0 = fmaxf(m0, mx0), nm1 = fmaxf(m1, mx1);
        float c0 = __expf(m0 - nm0), c1 = __expf(m1 - nm1);
        float s0 = 0.f, s1 = 0.f;
        #pragma unroll
        for (int nt = 0; nt < 8; nt++) {
            S[nt][0] = __expf(S[nt][0] - nm0);
            S[nt][1] = __expf(S[nt][1] - nm0);
            S[nt][2] = __expf(S[nt][2] - nm1);
            S[nt][3] = __expf(S[nt][3] - nm1);
            s0 += S[nt][0] + S[nt][1];
            s1 += S[nt][2] + S[nt][3];
        }
        s0 += __shfl_xor_sync(0xffffffffu, s0, 1);
        s0 += __shfl_xor_sync(0xffffffffu, s0, 2);
        s1 += __shfl_xor_sync(0xffffffffu, s1, 1);
        s1 += __shfl_xor_sync(0xffffffffu, s1, 2);
        m0 = nm0; m1 = nm1;
        l0 = l0 * c0 + s0;
        l1 = l1 * c1 + s1;
        #pragma unroll
        for (int nt = 0; nt < 8; nt++) {
            O[nt][0] *= c0; O[nt][1] *= c0;
            O[nt][2] *= c1; O[nt][3] *= c1;
        }

        // ---- O += P * V ----
        #pragma unroll
        for (int g = 0; g < 4; g++) {
            uint32_t ah[4];
            ah[0] = pack2h(S[2*g][0],   S[2*g][1]);
            ah[1] = pack2h(S[2*g][2],   S[2*g][3]);
            ah[2] = pack2h(S[2*g+1][0], S[2*g+1][1]);
            ah[3] = pack2h(S[2*g+1][2], S[2*g+1][3]);
            #pragma unroll
            for (int ntp = 0; ntp < 4; ntp++) {
                uint32_t vaddr = stgb + 9216u
                    + (uint32_t)(((g * 16 + (lane & 15)) * QS
                                  + ntp * 16 + ((lane >> 4) << 3)) * 2);
                uint32_t vh[4];
                ldm_x4t(vh, vaddr);
                mma_f16(O[2*ntp],   ah, vh);
                mma_f16(O[2*ntp+1], ah, vh + 2);
            }
        }
    }

    // Finalize: scale by SC_Y/l, store y as single fp16 for out-proj
    float il0 = SC_Y / l0, il1 = SC_Y / l1;
    int rowg = qt * 128 + r0 + (lane >> 2);
    #pragma unroll
    for (int nt = 0; nt < 8; nt++) {
        int hd = nt * 8 + (lane & 3) * 2;
        size_t o0 = (size_t)(b * Ln + rowg) * Dn + h * 64 + hd;
        size_t o1 = (size_t)(b * Ln + rowg + 8) * Dn + h * 64 + hd;
        *(uint32_t*)(g_y16 + o0) = pack2h(O[nt][0] * il0, O[nt][1] * il0);
        *(uint32_t*)(g_y16 + o1) = pack2h(O[nt][2] * il1, O[nt][3] * il1);
    }
}

// ---------------------------------------------------------------------------
extern "C" void kernel_launch(void* const* d_in, const int* in_sizes, int n_in,
                              void* d_out, int out_size)
{
    (void)in_sizes; (void)n_in; (void)out_size;
    const float* x  = (const float*)d_in[0];
    const float* Wq = (const float*)d_in[1];
    const float* Wk = (const float*)d_in[2];
    const float* Wv = (const float*)d_in[3];
    const float* Wo = (const float*)d_in[4];
    float* out = (float*)d_out;

    cudaFuncSetAttribute(gemm_mma_kernel,
                         cudaFuncAttributeMaxDynamicSharedMemorySize,
                         GEMM_SMEM_BYTES);
    cudaFuncSetAttribute(attn_kernel,
                         cudaFuncAttributeMaxDynamicSharedMemorySize,
                         ATTN_SMEM_BYTES);

    prep_kernel<<<8192, 256>>>(x, Wq, Wk, Wv, Wo);
    gemm_mma_kernel<<<dim3(Dn/128, NROW/128, 3), 256, GEMM_SMEM_BYTES>>>(nullptr, 0);
    attn_kernel<<<dim3(Ln/128, Hn, Bn), 256, ATTN_SMEM_BYTES>>>();
    gemm_mma_kernel<<<dim3(Dn/128, NROW/128, 1), 256, GEMM_SMEM_BYTES>>>(out, 1);
}